// round 1
// baseline (speedup 1.0000x reference)
#include <cuda_runtime.h>
#include <cstdint>

#define BB 4
#define NP 8192
#define MP 2048          // NP/4
#define KNN 16
#define CIN 64
#define CO 128
#define CG 67            // 3 + CIN
#define CGP 68           // padded
#define EPSBN 1e-5

// ---------------- scratch (static device allocations are allowed) -------------
__device__ int    g_sidx[BB * MP];
__device__ float  g_newp[BB * MP * 3];
__device__ float4 g_pts4[BB * NP];
__device__ int    g_nidx[BB * MP * KNN];
__device__ float  g_ymax[BB * MP * CO];
__device__ float  g_ymin[BB * MP * CO];
__device__ double g_sum[CO];
__device__ double g_sumsq[CO];
__device__ float  g_scale[CO];
__device__ float  g_meanv[CO];
__device__ float  g_shift[CO];

// ---------------- init: zero the BN accumulators (every replay) ----------------
__global__ void init_kernel() {
    int t = threadIdx.x;
    if (t < CO) { g_sum[t] = 0.0; g_sumsq[t] = 0.0; }
}

// ---------------- precompute (x,y,z,|p|^2) per point ---------------------------
__global__ void prep_kernel(const float* __restrict__ pt) {
    int i = blockIdx.x * 256 + threadIdx.x;
    if (i >= BB * NP) return;
    float x = pt[3 * i], y = pt[3 * i + 1], z = pt[3 * i + 2];
    // JAX: sum(p*p, -1) == (x*x + y*y) + z*z, no fma contraction
    float pp = __fadd_rn(__fadd_rn(__fmul_rn(x, x), __fmul_rn(y, y)), __fmul_rn(z, z));
    g_pts4[i] = make_float4(x, y, z, pp);
}

// ---------------- FPS: one CTA per batch, 1024 threads, 8 pts/thread -----------
extern __shared__ float fps_sm[];
__global__ void __launch_bounds__(1024, 1) fps_kernel(const float* __restrict__ pt) {
    float* sx = fps_sm;
    float* sy = fps_sm + NP;
    float* sz = fps_sm + 2 * NP;
    float* rv = fps_sm + 3 * NP;          // 32 warp maxima
    int*   ri = (int*)(rv + 32);          // 32 warp argmax
    int*   wsh = ri + 32;                 // winner broadcast

    const int b = blockIdx.x;
    const int t = threadIdx.x;
    const float* P = pt + (size_t)b * NP * 3;

    // stage coords in shared (coalesced read, scattered SoA write)
    for (int j = t; j < NP * 3; j += 1024) {
        float v = P[j];
        int p = j / 3, c = j - 3 * p;
        if (c == 0) sx[p] = v; else if (c == 1) sy[p] = v; else sz[p] = v;
    }
    __syncthreads();

    float px[8], py[8], pz[8], dist[8];
#pragma unroll
    for (int i = 0; i < 8; i++) {
        int g = t * 8 + i;
        px[i] = sx[g]; py[i] = sy[g]; pz[i] = sz[g];
        dist[i] = 1e10f;
    }
    float qx = sx[0], qy = sy[0], qz = sz[0];
    if (t == 0) {
        g_sidx[b * MP] = 0;
        int o = (b * MP) * 3;
        g_newp[o] = qx; g_newp[o + 1] = qy; g_newp[o + 2] = qz;
    }

    for (int it = 1; it < MP; it++) {
        float bv = -1.0f; int bi = 0;
#pragma unroll
        for (int i = 0; i < 8; i++) {
            // JAX-exact: d = ((dx*dx + dy*dy) + dz*dz), dist = min(dist, d)
            float dx = __fsub_rn(px[i], qx);
            float dy = __fsub_rn(py[i], qy);
            float dz = __fsub_rn(pz[i], qz);
            float d = __fadd_rn(__fadd_rn(__fmul_rn(dx, dx), __fmul_rn(dy, dy)),
                                __fmul_rn(dz, dz));
            float nd = fminf(dist[i], d);
            dist[i] = nd;
            if (nd > bv) { bv = nd; bi = t * 8 + i; }   // strict > keeps lowest idx on tie
        }
        // warp argmax (lowest global idx wins ties)
#pragma unroll
        for (int o = 16; o > 0; o >>= 1) {
            float ov = __shfl_down_sync(0xffffffffu, bv, o);
            int   oi = __shfl_down_sync(0xffffffffu, bi, o);
            if (ov > bv || (ov == bv && oi < bi)) { bv = ov; bi = oi; }
        }
        if ((t & 31) == 0) { rv[t >> 5] = bv; ri[t >> 5] = bi; }
        __syncthreads();
        if (t < 32) {
            float v = rv[t]; int idx = ri[t];
#pragma unroll
            for (int o = 16; o > 0; o >>= 1) {
                float ov = __shfl_down_sync(0xffffffffu, v, o);
                int   oi = __shfl_down_sync(0xffffffffu, idx, o);
                if (ov > v || (ov == v && oi < idx)) { v = ov; idx = oi; }
            }
            if (t == 0) {
                wsh[0] = idx;
                g_sidx[b * MP + it] = idx;
                int o = (b * MP + it) * 3;
                g_newp[o] = sx[idx]; g_newp[o + 1] = sy[idx]; g_newp[o + 2] = sz[idx];
            }
        }
        __syncthreads();
        int w = wsh[0];
        qx = sx[w]; qy = sy[w]; qz = sz[w];
    }
}

// ---------------- KNN: thread-per-query, 16-entry register heap ----------------
#define KT 2048   // point tile
__global__ void __launch_bounds__(128) knn_kernel() {
    __shared__ __align__(16) float4 tile[KT];
    const int m = blockIdx.x * 128 + threadIdx.x;       // global query id
    const int b = m / MP;

    const float q0 = g_newp[3 * m], q1 = g_newp[3 * m + 1], q2 = g_newp[3 * m + 2];
    const float qq = __fadd_rn(__fadd_rn(__fmul_rn(q0, q0), __fmul_rn(q1, q1)),
                               __fmul_rn(q2, q2));

    float bd[KNN]; int bix[KNN];
#pragma unroll
    for (int s = 0; s < KNN; s++) { bd[s] = 3.402823466e38f; bix[s] = 0x7fffffff; }
    float wv = 3.402823466e38f; int wIdx = 0x7fffffff; int wslot = 0;

    const float4* src = g_pts4 + (size_t)b * NP;
    for (int tb = 0; tb < NP / KT; tb++) {
        for (int j = threadIdx.x; j < KT; j += 128) tile[j] = src[tb * KT + j];
        __syncthreads();
        for (int jj = 0; jj < KT; jj++) {
            float4 p = tile[jj];
            // JAX: d2 = (qq + pp) - 2*(q . p)  with fma-chain dot
            float dot = __fmaf_rn(q2, p.z, __fmaf_rn(q1, p.y, __fmul_rn(q0, p.x)));
            float d2 = __fsub_rn(__fadd_rn(qq, p.w), __fmul_rn(2.0f, dot));
            if (d2 < wv) {                        // strict: ties keep earlier index
                int j = tb * KT + jj;
#pragma unroll
                for (int s = 0; s < KNN; s++)
                    if (s == wslot) { bd[s] = d2; bix[s] = j; }
                wv = bd[0]; wIdx = bix[0]; wslot = 0;
#pragma unroll
                for (int s = 1; s < KNN; s++)
                    if (bd[s] > wv || (bd[s] == wv && bix[s] > wIdx)) {
                        wv = bd[s]; wIdx = bix[s]; wslot = s;
                    }
            }
        }
        __syncthreads();
    }
#pragma unroll
    for (int s = 0; s < KNN; s++) g_nidx[m * KNN + s] = bix[s];
}

// ---------------- group + linear + channel stats + k-max/min -------------------
__global__ void __launch_bounds__(128) group_kernel(const float* __restrict__ feat,
                                                    const float* __restrict__ Wm) {
    __shared__ __align__(16) float sW[CO * CG];
    __shared__ __align__(16) float sg[KNN][CGP];
    __shared__ int snb[KNN];

    const int tid = threadIdx.x;
    const int o = tid;
    for (int j = tid; j < CO * CG; j += 128) sW[j] = Wm[j];
    __syncthreads();

    float w[CGP];
#pragma unroll
    for (int c = 0; c < CG; c++) w[c] = sW[o * CG + c];
    w[CG] = 0.0f;

    double lsum = 0.0, lsq = 0.0;
    const int m0 = blockIdx.x * 8;

    for (int mi = 0; mi < 8; mi++) {
        const int m = m0 + mi;
        const int b = m / MP;
        if (tid < KNN) snb[tid] = g_nidx[m * KNN + tid];
        __syncthreads();

        // relative xyz (JAX-exact sub) + zero pad
        if (tid < KNN) {
            float4 p = g_pts4[(size_t)b * NP + snb[tid]];
            sg[tid][0] = __fsub_rn(p.x, g_newp[3 * m]);
            sg[tid][1] = __fsub_rn(p.y, g_newp[3 * m + 1]);
            sg[tid][2] = __fsub_rn(p.z, g_newp[3 * m + 2]);
            sg[tid][CG] = 0.0f;
        }
        // features: 16 rows x 64, 8 floats per thread
        {
            int k = tid >> 3, c0 = (tid & 7) << 3;
            const float* fr = feat + ((size_t)b * NP + snb[k]) * CIN + c0;
            float4 a = *(const float4*)fr;
            float4 bq = *(const float4*)(fr + 4);
            sg[k][3 + c0 + 0] = a.x;  sg[k][3 + c0 + 1] = a.y;
            sg[k][3 + c0 + 2] = a.z;  sg[k][3 + c0 + 3] = a.w;
            sg[k][3 + c0 + 4] = bq.x; sg[k][3 + c0 + 5] = bq.y;
            sg[k][3 + c0 + 6] = bq.z; sg[k][3 + c0 + 7] = bq.w;
        }
        __syncthreads();

        float ymx = -3.402823466e38f, ymn = 3.402823466e38f;
#pragma unroll 1
        for (int k = 0; k < KNN; k++) {
            const float4* gr = (const float4*)sg[k];
            float acc = 0.0f;
#pragma unroll
            for (int c4 = 0; c4 < CGP / 4; c4++) {
                float4 gv = gr[c4];
                acc = __fmaf_rn(gv.x, w[4 * c4 + 0], acc);
                acc = __fmaf_rn(gv.y, w[4 * c4 + 1], acc);
                acc = __fmaf_rn(gv.z, w[4 * c4 + 2], acc);
                acc = __fmaf_rn(gv.w, w[4 * c4 + 3], acc);
            }
            ymx = fmaxf(ymx, acc);
            ymn = fminf(ymn, acc);
            lsum += (double)acc;
            lsq = fma((double)acc, (double)acc, lsq);
        }
        g_ymax[m * CO + o] = ymx;
        g_ymin[m * CO + o] = ymn;
        __syncthreads();
    }
    atomicAdd(&g_sum[o], lsum);
    atomicAdd(&g_sumsq[o], lsq);
}

// ---------------- BN statistics finalize ----------------------------------------
__global__ void stats_kernel(const float* __restrict__ gamma,
                             const float* __restrict__ beta) {
    int o = threadIdx.x;
    if (o >= CO) return;
    const double n = (double)BB * MP * KNN;
    double mean = g_sum[o] / n;
    double var = g_sumsq[o] / n - mean * mean;
    if (var < 0.0) var = 0.0;
    double s = (double)gamma[o] / sqrt(var + EPSBN);
    g_scale[o] = (float)s;
    g_meanv[o] = (float)mean;
    g_shift[o] = beta[o];
}

// ---------------- output: relu(max_k BN(y)) via max/min trick -------------------
__global__ void out_kernel(float* __restrict__ dst) {
    int idx = blockIdx.x * 256 + threadIdx.x;
    if (idx >= BB * MP * CO) return;
    int o = idx & (CO - 1);
    float s = g_scale[o];
    float v = (s >= 0.0f) ? g_ymax[idx] : g_ymin[idx];
    float t = __fsub_rn(v, g_meanv[o]);
    float r = __fadd_rn(__fmul_rn(t, s), g_shift[o]);
    dst[idx] = fmaxf(r, 0.0f);
}

__global__ void copy_np_kernel(float* __restrict__ dst) {
    int i = blockIdx.x * 256 + threadIdx.x;
    if (i < BB * MP * 3) dst[i] = g_newp[i];
}

__global__ void splits_f32_kernel(float* __restrict__ dst) {
    int i = threadIdx.x;
    if (i <= BB) dst[i] = (float)(i * MP);
}
__global__ void splits_i64_kernel(long long* __restrict__ dst) {
    int i = threadIdx.x;
    if (i <= BB) dst[i] = (long long)i * MP;
}

// ---------------- launch ---------------------------------------------------------
extern "C" void kernel_launch(void* const* d_in, const int* in_sizes, int n_in,
                              void* d_out, int out_size) {
    const float* point = (const float*)d_in[0];
    const float* feat  = (const float*)d_in[1];
    const float* Wm    = (const float*)d_in[3];
    const float* gamma = (const float*)d_in[4];
    const float* beta  = (const float*)d_in[5];
    float* out = (float*)d_out;

    const int FPS_SMEM = 3 * NP * 4 + 1024;
    cudaFuncSetAttribute(fps_kernel, cudaFuncAttributeMaxDynamicSharedMemorySize, FPS_SMEM);

    init_kernel<<<1, 128>>>();
    prep_kernel<<<(BB * NP + 255) / 256, 256>>>(point);
    fps_kernel<<<BB, 1024, FPS_SMEM>>>(point);
    knn_kernel<<<BB * MP / 128, 128>>>();
    group_kernel<<<BB * MP / 8, 128>>>(feat, Wm);
    stats_kernel<<<1, 128>>>(gamma, beta);

    const int NPT = BB * MP * 3;          // 24576
    const int NFT = BB * MP * CO;         // 1048576
    int feat_off = 0;
    bool write_pts = false;
    if (out_size >= NPT + NFT) { write_pts = true; feat_off = NPT; }

    out_kernel<<<(NFT + 255) / 256, 256>>>(out + feat_off);
    if (write_pts) copy_np_kernel<<<(NPT + 255) / 256, 256>>>(out);

    int rem = out_size - feat_off - NFT;
    if (rem == BB + 1) {
        splits_f32_kernel<<<1, 32>>>(out + feat_off + NFT);
    } else if (rem == 2 * (BB + 1)) {
        splits_i64_kernel<<<1, 32>>>((long long*)(out + feat_off + NFT));
    }
}